// round 6
// baseline (speedup 1.0000x reference)
#include <cuda_runtime.h>
#include <cuda_bf16.h>
#include <cstdint>

// ---------------------------------------------------------------------------
// GCN: 3x (pointwise -> bf16x3 mma.sync GEMM -> CSR gather-sum) + mean pool
// GEMM first (row scaling commutes with @W; segment-sum is linear).
// Aggregation is PULL-based over a per-launch CSR (dst-sorted edges):
// no global atomics in the hot path, AGG rows written exactly once.
// R5->R6: gather inner loop unrolled x4 with 4 independent accumulators (MLP).
// ---------------------------------------------------------------------------

#define MAX_NODES 100000
#define MAX_EDGES 1600000
#define MAX_FEATS 128
#define SCAN_BS 512

__device__ float g_X[MAX_NODES * MAX_FEATS];    // GEMM outputs (pre-gather)
__device__ float g_AGG[MAX_NODES * MAX_FEATS];  // gathered sums
__device__ float g_outnorm[MAX_NODES];
__device__ float g_innorm[MAX_NODES];
__device__ int   g_indeg[MAX_NODES];
__device__ int   g_outdeg[MAX_NODES];
__device__ int   g_rowptr[MAX_NODES + 1];
__device__ int   g_fill[MAX_NODES];
__device__ int   g_col[MAX_EDGES];
__device__ int   g_bsums[(MAX_NODES + SCAN_BS - 1) / SCAN_BS];

// ----------------------------- helpers -------------------------------------

__device__ __forceinline__ uint32_t smem_u32(const void* p) {
    uint32_t a;
    asm("{ .reg .u64 t; cvta.to.shared.u64 t, %1; cvt.u32.u64 %0, t; }" : "=r"(a) : "l"(p));
    return a;
}

__device__ __forceinline__ void ldsm_x4(uint32_t* r, uint32_t addr) {
    asm volatile("ldmatrix.sync.aligned.m8n8.x4.shared.b16 {%0,%1,%2,%3}, [%4];"
                 : "=r"(r[0]), "=r"(r[1]), "=r"(r[2]), "=r"(r[3]) : "r"(addr));
}

__device__ __forceinline__ void mma_bf16(float* d, const uint32_t* a, const uint32_t* b) {
    asm volatile("mma.sync.aligned.m16n8k16.row.col.f32.bf16.bf16.f32 "
                 "{%0,%1,%2,%3}, {%4,%5,%6,%7}, {%8,%9}, {%0,%1,%2,%3};"
                 : "+f"(d[0]), "+f"(d[1]), "+f"(d[2]), "+f"(d[3])
                 : "r"(a[0]), "r"(a[1]), "r"(a[2]), "r"(a[3]), "r"(b[0]), "r"(b[1]));
}

__device__ __forceinline__ void split2(float x, float y, uint32_t& hi, uint32_t& lo) {
    __nv_bfloat162 h = __floats2bfloat162_rn(x, y);
    float rx = x - __bfloat162float(h.x);
    float ry = y - __bfloat162float(h.y);
    __nv_bfloat162 l = __floats2bfloat162_rn(rx, ry);
    hi = reinterpret_cast<uint32_t&>(h);
    lo = reinterpret_cast<uint32_t&>(l);
}

__device__ __forceinline__ void split1(float x, uint16_t& hi, uint16_t& lo) {
    __nv_bfloat16 h = __float2bfloat16_rn(x);
    float r = x - __bfloat162float(h);
    __nv_bfloat16 l = __float2bfloat16_rn(r);
    hi = reinterpret_cast<uint16_t&>(h);
    lo = reinterpret_cast<uint16_t&>(l);
}

// --------------------------- CSR construction ------------------------------

__global__ void zero_int2_kernel(int* __restrict__ a, int* __restrict__ b, int n) {
    int i = blockIdx.x * blockDim.x + threadIdx.x;
    if (i < n) { a[i] = 0; b[i] = 0; }
}

__global__ void hist_kernel(const int* __restrict__ src, const int* __restrict__ dst,
                            int* __restrict__ outdeg, int* __restrict__ indeg, int E) {
    int i = blockIdx.x * blockDim.x + threadIdx.x;
    if (i < E) {
        atomicAdd(outdeg + src[i], 1);
        atomicAdd(indeg + dst[i], 1);
    }
}

__global__ void scanA_kernel(const int* __restrict__ deg, int* __restrict__ rowptr,
                             int* __restrict__ bsums, int n) {
    __shared__ int sh[SCAN_BS];
    int t = threadIdx.x;
    int i = blockIdx.x * SCAN_BS + t;
    int v = (i < n) ? deg[i] : 0;
    sh[t] = v;
    __syncthreads();
#pragma unroll
    for (int off = 1; off < SCAN_BS; off <<= 1) {
        int x = (t >= off) ? sh[t - off] : 0;
        __syncthreads();
        sh[t] += x;
        __syncthreads();
    }
    if (i < n) rowptr[i] = sh[t] - v;
    if (t == SCAN_BS - 1) bsums[blockIdx.x] = sh[t];
}

__global__ void scanB_kernel(int* __restrict__ bsums, int nb) {
    __shared__ int sh[256];
    int t = threadIdx.x;
    int v = (t < nb) ? bsums[t] : 0;
    sh[t] = v;
    __syncthreads();
#pragma unroll
    for (int off = 1; off < 256; off <<= 1) {
        int x = (t >= off) ? sh[t - off] : 0;
        __syncthreads();
        sh[t] += x;
        __syncthreads();
    }
    if (t < nb) bsums[t] = sh[t] - v;
}

__global__ void scanC_kernel(int* __restrict__ rowptr, int* __restrict__ fill,
                             const int* __restrict__ bsums, int n, int E) {
    int i = blockIdx.x * blockDim.x + threadIdx.x;
    if (i < n) {
        int r = rowptr[i] + bsums[i / SCAN_BS];
        rowptr[i] = r;
        fill[i] = r;
    }
    if (i == 0) rowptr[n] = E;
}

__global__ void fill_kernel(const int* __restrict__ src, const int* __restrict__ dst,
                            int* __restrict__ fill, int* __restrict__ col, int E) {
    int i = blockIdx.x * blockDim.x + threadIdx.x;
    if (i < E) {
        int p = atomicAdd(fill + dst[i], 1);
        col[p] = src[i];
    }
}

__global__ void norm_kernel(const int* __restrict__ od, const int* __restrict__ id,
                            float* __restrict__ onrm, float* __restrict__ inrm, int n) {
    int i = blockIdx.x * blockDim.x + threadIdx.x;
    if (i < n) {
        onrm[i] = rsqrtf(fmaxf((float)od[i], 1.0f));
        inrm[i] = rsqrtf(fmaxf((float)id[i], 1.0f));
    }
}

// --------------------------- bf16x3 GEMM -----------------------------------
// X[M,N] = f(A[M,K]) @ W[K,N], CTA tile 128 x N, K chunks of 32, 256 threads.
// MODE 0: f(a)[r,k] = a[r,k] * outnorm[r]
// MODE 1: f(a)[r,k] = relu(a[r,k]*innorm[r] + bprev[k]) * outnorm[r]
// bf16x3: D = Ah@Bh + Ah@Bl + Al@Bh, fp32 accum (mma.sync m16n8k16).

template<int K, int N, int MODE>
__global__ __launch_bounds__(256)
void gemm_mma_kernel(const float* __restrict__ A, const float* __restrict__ W,
                     const float* __restrict__ bprev,
                     const float* __restrict__ outnorm, const float* __restrict__ innorm,
                     float* __restrict__ X, int M) {
    constexpr int BK = 32;
    constexpr int NCHUNK = K / BK;
    constexpr int WN = N / 2;
    constexpr int NT = WN / 8;
    constexpr int MT = 2;
    constexpr int P = 40;            // smem pitch in bf16 (80B, LDSM-clean)
    constexpr int A_HI = 0;
    constexpr int A_LO = 128 * P * 2;
    constexpr int W_HI = 2 * A_LO;
    constexpr int W_SZ = N * P * 2;
    constexpr int W_LO = W_HI + W_SZ;
    constexpr int BUFS = W_LO + W_SZ;
    constexpr int WE = N / 8;
    constexpr int LOGN = (N == 128) ? 7 : 6;

    extern __shared__ char smem[];
    const uint32_t sb = smem_u32(smem);
    const int tid = threadIdx.x;
    const int lane = tid & 31;
    const int wid = tid >> 5;
    const int warp_m = wid >> 1;
    const int warp_n = wid & 1;
    const int row0 = blockIdx.x * 128;

    const int arow = tid & 127;
    const int ahalf = tid >> 7;
    const int grow = row0 + arow;
    const bool valid = grow < M;
    const float on  = valid ? outnorm[grow] : 0.f;
    const float inn = (MODE == 1 && valid) ? innorm[grow] : 0.f;

    const int a_r = warp_m * 32 + ((lane >> 3) & 1) * 8 + (lane & 7);
    const int a_k = (lane >> 4) * 8;
    const int b_n = warp_n * WN + (lane >> 4) * 8 + (lane & 7);
    const int b_k = ((lane >> 3) & 1) * 8;

    float acc[MT][NT][4];
#pragma unroll
    for (int i = 0; i < MT; i++)
#pragma unroll
        for (int j = 0; j < NT; j++)
#pragma unroll
            for (int q = 0; q < 4; q++) acc[i][j][q] = 0.f;

    float4 av[4];
    float wv[WE];

    auto load_g = [&](int c) {
        const int kc = c * BK;
#pragma unroll
        for (int q = 0; q < 4; q++) {
            const int col = ahalf * 16 + q * 4;
            float4 v = make_float4(0.f, 0.f, 0.f, 0.f);
            if (valid) {
                v = *reinterpret_cast<const float4*>(A + (size_t)grow * K + kc + col);
                if (MODE == 0) {
                    v.x *= on; v.y *= on; v.z *= on; v.w *= on;
                } else {
                    float4 b = *reinterpret_cast<const float4*>(bprev + kc + col);
                    v.x = fmaxf(fmaf(v.x, inn, b.x), 0.f) * on;
                    v.y = fmaxf(fmaf(v.y, inn, b.y), 0.f) * on;
                    v.z = fmaxf(fmaf(v.z, inn, b.z), 0.f) * on;
                    v.w = fmaxf(fmaf(v.w, inn, b.w), 0.f) * on;
                }
            }
            av[q] = v;
        }
#pragma unroll
        for (int e = 0; e < WE; e++) {
            const int elem = tid + e * 256;
            const int n = elem & (N - 1);
            const int kk = elem >> LOGN;
            wv[e] = __ldg(W + (size_t)(kc + kk) * N + n);
        }
    };

    auto store_s = [&](int buf) {
        char* base = smem + buf * BUFS;
#pragma unroll
        for (int q = 0; q < 4; q++) {
            const int col = ahalf * 16 + q * 4;
            uint32_t h01, l01, h23, l23;
            split2(av[q].x, av[q].y, h01, l01);
            split2(av[q].z, av[q].w, h23, l23);
            const uint32_t off = (uint32_t)arow * (P * 2) + col * 2;
            *reinterpret_cast<uint2*>(base + A_HI + off) = make_uint2(h01, h23);
            *reinterpret_cast<uint2*>(base + A_LO + off) = make_uint2(l01, l23);
        }
#pragma unroll
        for (int e = 0; e < WE; e++) {
            const int elem = tid + e * 256;
            const int n = elem & (N - 1);
            const int kk = elem >> LOGN;
            uint16_t h, l;
            split1(wv[e], h, l);
            const uint32_t off = (uint32_t)n * (P * 2) + kk * 2;
            *reinterpret_cast<uint16_t*>(base + W_HI + off) = h;
            *reinterpret_cast<uint16_t*>(base + W_LO + off) = l;
        }
    };

    auto compute = [&](int buf) {
        const uint32_t ab = sb + buf * BUFS;
#pragma unroll
        for (int ks = 0; ks < 2; ks++) {
            uint32_t ah[MT][4], al[MT][4];
#pragma unroll
            for (int i = 0; i < MT; i++) {
                const uint32_t addr = ab + A_HI +
                    (uint32_t)(a_r + i * 16) * (P * 2) + (a_k + ks * 16) * 2;
                ldsm_x4(ah[i], addr);
                ldsm_x4(al[i], addr + A_LO);
            }
#pragma unroll
            for (int p = 0; p < NT / 2; p++) {
                uint32_t bh[4], bl[4];
                const uint32_t baddr = ab + W_HI +
                    (uint32_t)(b_n + p * 16) * (P * 2) + (b_k + ks * 16) * 2;
                ldsm_x4(bh, baddr);
                ldsm_x4(bl, baddr + W_SZ);
#pragma unroll
                for (int i = 0; i < MT; i++)
#pragma unroll
                    for (int jj = 0; jj < 2; jj++) {
                        float* d = acc[i][p * 2 + jj];
                        mma_bf16(d, ah[i], bh + jj * 2);
                        mma_bf16(d, ah[i], bl + jj * 2);
                        mma_bf16(d, al[i], bh + jj * 2);
                    }
            }
        }
    };

    load_g(0);
    store_s(0);
    __syncthreads();

    for (int c = 0; c < NCHUNK; c++) {
        if (c + 1 < NCHUNK) load_g(c + 1);
        compute(c & 1);
        if (c + 1 < NCHUNK) store_s((c + 1) & 1);
        __syncthreads();
    }

#pragma unroll
    for (int i = 0; i < MT; i++) {
        const int r0 = row0 + warp_m * 32 + i * 16 + (lane >> 2);
#pragma unroll
        for (int j = 0; j < NT; j++) {
            const int n0 = warp_n * WN + j * 8 + (lane & 3) * 2;
            if (r0 < M)
                *reinterpret_cast<float2*>(X + (size_t)r0 * N + n0) =
                    make_float2(acc[i][j][0], acc[i][j][1]);
            if (r0 + 8 < M)
                *reinterpret_cast<float2*>(X + (size_t)(r0 + 8) * N + n0) =
                    make_float2(acc[i][j][2], acc[i][j][3]);
        }
    }
}

// ------------------------------ CSR gather ---------------------------------
// AGG[n] = sum over e in [rowptr[n], rowptr[n+1]) of X[col[e]]
// D/4 lanes per node, one float4 per lane.
// 4-edge unroll with 4 independent accumulators -> 4-deep load MLP per lane.

template<int D>
__global__ __launch_bounds__(256)
void gather_kernel(const float* __restrict__ X, const int* __restrict__ rowptr,
                   const int* __restrict__ col, float* __restrict__ AGG, int Nn) {
    constexpr int LPN = D / 4;
    int t = blockIdx.x * blockDim.x + threadIdx.x;
    int node = t / LPN;
    if (node >= Nn) return;
    int c = (t % LPN) * 4;
    int beg = __ldg(rowptr + node);
    int end = __ldg(rowptr + node + 1);

    float4 a0 = make_float4(0.f, 0.f, 0.f, 0.f);
    float4 a1 = make_float4(0.f, 0.f, 0.f, 0.f);
    float4 a2 = make_float4(0.f, 0.f, 0.f, 0.f);
    float4 a3 = make_float4(0.f, 0.f, 0.f, 0.f);

    int e = beg;
    for (; e + 3 < end; e += 4) {
        int s0 = __ldg(col + e);
        int s1 = __ldg(col + e + 1);
        int s2 = __ldg(col + e + 2);
        int s3 = __ldg(col + e + 3);
        float4 v0 = __ldg(reinterpret_cast<const float4*>(X + (size_t)s0 * D + c));
        float4 v1 = __ldg(reinterpret_cast<const float4*>(X + (size_t)s1 * D + c));
        float4 v2 = __ldg(reinterpret_cast<const float4*>(X + (size_t)s2 * D + c));
        float4 v3 = __ldg(reinterpret_cast<const float4*>(X + (size_t)s3 * D + c));
        a0.x += v0.x; a0.y += v0.y; a0.z += v0.z; a0.w += v0.w;
        a1.x += v1.x; a1.y += v1.y; a1.z += v1.z; a1.w += v1.w;
        a2.x += v2.x; a2.y += v2.y; a2.z += v2.z; a2.w += v2.w;
        a3.x += v3.x; a3.y += v3.y; a3.z += v3.z; a3.w += v3.w;
    }
    if (e + 1 < end) {
        int s0 = __ldg(col + e);
        int s1 = __ldg(col + e + 1);
        float4 v0 = __ldg(reinterpret_cast<const float4*>(X + (size_t)s0 * D + c));
        float4 v1 = __ldg(reinterpret_cast<const float4*>(X + (size_t)s1 * D + c));
        a0.x += v0.x; a0.y += v0.y; a0.z += v0.z; a0.w += v0.w;
        a1.x += v1.x; a1.y += v1.y; a1.z += v1.z; a1.w += v1.w;
        e += 2;
    }
    if (e < end) {
        int s0 = __ldg(col + e);
        float4 v0 = __ldg(reinterpret_cast<const float4*>(X + (size_t)s0 * D + c));
        a2.x += v0.x; a2.y += v0.y; a2.z += v0.z; a2.w += v0.w;
    }

    float4 r;
    r.x = (a0.x + a1.x) + (a2.x + a3.x);
    r.y = (a0.y + a1.y) + (a2.y + a3.y);
    r.z = (a0.z + a1.z) + (a2.z + a3.z);
    r.w = (a0.w + a1.w) + (a2.w + a3.w);
    *reinterpret_cast<float4*>(AGG + (size_t)node * D + c) = r;
}

// ------------------------------- pooling -----------------------------------

__device__ __forceinline__ int lower_bound_dev(const int* __restrict__ a, int n, int v) {
    int lo = 0, hi = n;
    while (lo < hi) {
        int m = (lo + hi) >> 1;
        if (a[m] < v) lo = m + 1; else hi = m;
    }
    return lo;
}

__global__ void pool_kernel(const float* __restrict__ AGG, const float* __restrict__ innorm,
                            const float* __restrict__ b3, const int* __restrict__ gids,
                            float* __restrict__ out, int Nn) {
    int g = blockIdx.x;
    int lo = lower_bound_dev(gids, Nn, g);
    int hi = lower_bound_dev(gids, Nn, g + 1);
    int f = threadIdx.x & 63;
    int slot = threadIdx.x >> 6;
    float bf = b3[f];
    float sum = 0.f;
    for (int i = lo + slot; i < hi; i += 4)
        sum += fmaf(AGG[(size_t)i * 64 + f], innorm[i], bf);
    __shared__ float sh[256];
    sh[threadIdx.x] = sum;
    __syncthreads();
    if (slot == 0) {
        float tot = sh[f] + sh[64 + f] + sh[128 + f] + sh[192 + f];
        float cnt = (float)(hi - lo);
        out[g * 64 + f] = tot / fmaxf(cnt, 1.f);
    }
}

// ------------------------------- launch ------------------------------------

extern "C" void kernel_launch(void* const* d_in, const int* in_sizes, int n_in,
                              void* d_out, int out_size) {
    const float* emb = (const float*)d_in[0];
    const float* W1  = (const float*)d_in[1];
    const float* b1  = (const float*)d_in[2];
    const float* W2  = (const float*)d_in[3];
    const float* b2  = (const float*)d_in[4];
    const float* W3  = (const float*)d_in[5];
    const float* b3  = (const float*)d_in[6];
    const int*   src = (const int*)d_in[7];
    const int*   dst = (const int*)d_in[8];
    const int*   gid = (const int*)d_in[9];
    float* out = (float*)d_out;

    const int Nn = in_sizes[0] / 128;   // 100000
    const int E  = in_sizes[7];         // 1600000
    const int G  = out_size / 64;       // 64

    float *X, *AGG, *onrm, *inrm;
    int *indeg, *outdeg, *rowptr, *fillc, *colA, *bsums;
    cudaGetSymbolAddress((void**)&X,      g_X);
    cudaGetSymbolAddress((void**)&AGG,    g_AGG);
    cudaGetSymbolAddress((void**)&onrm,   g_outnorm);
    cudaGetSymbolAddress((void**)&inrm,   g_innorm);
    cudaGetSymbolAddress((void**)&indeg,  g_indeg);
    cudaGetSymbolAddress((void**)&outdeg, g_outdeg);
    cudaGetSymbolAddress((void**)&rowptr, g_rowptr);
    cudaGetSymbolAddress((void**)&fillc,  g_fill);
    cudaGetSymbolAddress((void**)&colA,   g_col);
    cudaGetSymbolAddress((void**)&bsums,  g_bsums);

    const int smem128 = 2 * (20480 + 2 * 128 * 80);  // 81920
    const int smem64  = 2 * (20480 + 2 * 64 * 80);   // 61440
    cudaFuncSetAttribute(gemm_mma_kernel<128, 128, 0>,
                         cudaFuncAttributeMaxDynamicSharedMemorySize, smem128);
    cudaFuncSetAttribute(gemm_mma_kernel<128, 64, 1>,
                         cudaFuncAttributeMaxDynamicSharedMemorySize, smem64);
    cudaFuncSetAttribute(gemm_mma_kernel<64, 64, 1>,
                         cudaFuncAttributeMaxDynamicSharedMemorySize, smem64);

    const int T = 256;
    const int gemm_grid = (Nn + 127) / 128;
    const int nb_scan = (Nn + SCAN_BS - 1) / SCAN_BS;

    // ---- CSR build + norms ----
    zero_int2_kernel<<<(Nn + T - 1) / T, T>>>(indeg, outdeg, Nn);
    hist_kernel<<<(E + T - 1) / T, T>>>(src, dst, outdeg, indeg, E);
    scanA_kernel<<<nb_scan, SCAN_BS>>>(indeg, rowptr, bsums, Nn);
    scanB_kernel<<<1, 256>>>(bsums, nb_scan);
    scanC_kernel<<<(Nn + T - 1) / T, T>>>(rowptr, fillc, bsums, Nn, E);
    norm_kernel<<<(Nn + T - 1) / T, T>>>(outdeg, indeg, onrm, inrm, Nn);
    fill_kernel<<<(E + T - 1) / T, T>>>(src, dst, fillc, colA, E);

    // Layer 1: X1 = (emb * outnorm) @ W1 ; agg1 = gather(X1)
    gemm_mma_kernel<128, 128, 0><<<gemm_grid, T, smem128>>>(emb, W1, nullptr, onrm, inrm, X, Nn);
    gather_kernel<128><<<(Nn * 32 + T - 1) / T, T>>>(X, rowptr, colA, AGG, Nn);

    // Layer 2: X2 = relu(agg1*innorm + b1)*outnorm @ W2 ; agg2 = gather(X2)
    gemm_mma_kernel<128, 64, 1><<<gemm_grid, T, smem64>>>(AGG, W2, b1, onrm, inrm, X, Nn);
    gather_kernel<64><<<(Nn * 16 + T - 1) / T, T>>>(X, rowptr, colA, AGG, Nn);

    // Layer 3: X3 = relu(agg2*innorm + b2)*outnorm @ W3 ; agg3 = gather(X3)
    gemm_mma_kernel<64, 64, 1><<<gemm_grid, T, smem64>>>(AGG, W3, b2, onrm, inrm, X, Nn);
    gather_kernel<64><<<(Nn * 16 + T - 1) / T, T>>>(X, rowptr, colA, AGG, Nn);

    // Pool
    pool_kernel<<<G, T>>>(AGG, inrm, b3, gid, out, Nn);
}

// round 7
// speedup vs baseline: 1.0902x; 1.0902x over previous
#include <cuda_runtime.h>
#include <cuda_bf16.h>
#include <cuda_fp16.h>
#include <cstdint>

// ---------------------------------------------------------------------------
// GCN: 3x (pointwise -> bf16x3 mma.sync GEMM -> CSR gather-sum) + mean pool
// GEMM first (row scaling commutes with @W; segment-sum is linear).
// Aggregation is PULL-based over a per-launch CSR (dst-sorted edges).
// R6->R7: X stored as fp16 (halves gather L2 traffic); gather back to 2-unroll;
// norms folded into scanC.
// ---------------------------------------------------------------------------

#define MAX_NODES 100000
#define MAX_EDGES 1600000
#define MAX_FEATS 128
#define SCAN_BS 512

__device__ __half g_X[MAX_NODES * MAX_FEATS];   // GEMM outputs, fp16 (gather input)
__device__ float  g_AGG[MAX_NODES * MAX_FEATS]; // gathered sums, fp32
__device__ float  g_outnorm[MAX_NODES];
__device__ float  g_innorm[MAX_NODES];
__device__ int    g_indeg[MAX_NODES];
__device__ int    g_outdeg[MAX_NODES];
__device__ int    g_rowptr[MAX_NODES + 1];
__device__ int    g_fill[MAX_NODES];
__device__ int    g_col[MAX_EDGES];
__device__ int    g_bsums[(MAX_NODES + SCAN_BS - 1) / SCAN_BS];

// ----------------------------- helpers -------------------------------------

__device__ __forceinline__ uint32_t smem_u32(const void* p) {
    uint32_t a;
    asm("{ .reg .u64 t; cvta.to.shared.u64 t, %1; cvt.u32.u64 %0, t; }" : "=r"(a) : "l"(p));
    return a;
}

__device__ __forceinline__ void ldsm_x4(uint32_t* r, uint32_t addr) {
    asm volatile("ldmatrix.sync.aligned.m8n8.x4.shared.b16 {%0,%1,%2,%3}, [%4];"
                 : "=r"(r[0]), "=r"(r[1]), "=r"(r[2]), "=r"(r[3]) : "r"(addr));
}

__device__ __forceinline__ void mma_bf16(float* d, const uint32_t* a, const uint32_t* b) {
    asm volatile("mma.sync.aligned.m16n8k16.row.col.f32.bf16.bf16.f32 "
                 "{%0,%1,%2,%3}, {%4,%5,%6,%7}, {%8,%9}, {%0,%1,%2,%3};"
                 : "+f"(d[0]), "+f"(d[1]), "+f"(d[2]), "+f"(d[3])
                 : "r"(a[0]), "r"(a[1]), "r"(a[2]), "r"(a[3]), "r"(b[0]), "r"(b[1]));
}

__device__ __forceinline__ void split2(float x, float y, uint32_t& hi, uint32_t& lo) {
    __nv_bfloat162 h = __floats2bfloat162_rn(x, y);
    float rx = x - __bfloat162float(h.x);
    float ry = y - __bfloat162float(h.y);
    __nv_bfloat162 l = __floats2bfloat162_rn(rx, ry);
    hi = reinterpret_cast<uint32_t&>(h);
    lo = reinterpret_cast<uint32_t&>(l);
}

__device__ __forceinline__ void split1(float x, uint16_t& hi, uint16_t& lo) {
    __nv_bfloat16 h = __float2bfloat16_rn(x);
    float r = x - __bfloat162float(h);
    __nv_bfloat16 l = __float2bfloat16_rn(r);
    hi = reinterpret_cast<uint16_t&>(h);
    lo = reinterpret_cast<uint16_t&>(l);
}

// --------------------------- CSR construction ------------------------------

__global__ void zero_int2_kernel(int* __restrict__ a, int* __restrict__ b, int n) {
    int i = blockIdx.x * blockDim.x + threadIdx.x;
    if (i < n) { a[i] = 0; b[i] = 0; }
}

__global__ void hist_kernel(const int* __restrict__ src, const int* __restrict__ dst,
                            int* __restrict__ outdeg, int* __restrict__ indeg, int E) {
    int i = blockIdx.x * blockDim.x + threadIdx.x;
    if (i < E) {
        atomicAdd(outdeg + src[i], 1);
        atomicAdd(indeg + dst[i], 1);
    }
}

__global__ void scanA_kernel(const int* __restrict__ deg, int* __restrict__ rowptr,
                             int* __restrict__ bsums, int n) {
    __shared__ int sh[SCAN_BS];
    int t = threadIdx.x;
    int i = blockIdx.x * SCAN_BS + t;
    int v = (i < n) ? deg[i] : 0;
    sh[t] = v;
    __syncthreads();
#pragma unroll
    for (int off = 1; off < SCAN_BS; off <<= 1) {
        int x = (t >= off) ? sh[t - off] : 0;
        __syncthreads();
        sh[t] += x;
        __syncthreads();
    }
    if (i < n) rowptr[i] = sh[t] - v;
    if (t == SCAN_BS - 1) bsums[blockIdx.x] = sh[t];
}

__global__ void scanB_kernel(int* __restrict__ bsums, int nb) {
    __shared__ int sh[256];
    int t = threadIdx.x;
    int v = (t < nb) ? bsums[t] : 0;
    sh[t] = v;
    __syncthreads();
#pragma unroll
    for (int off = 1; off < 256; off <<= 1) {
        int x = (t >= off) ? sh[t - off] : 0;
        __syncthreads();
        sh[t] += x;
        __syncthreads();
    }
    if (t < nb) bsums[t] = sh[t] - v;
}

// Phase C: finalize rowptr/fill cursors AND node norms (fused).
__global__ void scanC_kernel(int* __restrict__ rowptr, int* __restrict__ fill,
                             const int* __restrict__ bsums,
                             const int* __restrict__ outdeg, const int* __restrict__ indeg,
                             float* __restrict__ onrm, float* __restrict__ inrm,
                             int n, int E) {
    int i = blockIdx.x * blockDim.x + threadIdx.x;
    if (i < n) {
        int r = rowptr[i] + bsums[i / SCAN_BS];
        rowptr[i] = r;
        fill[i] = r;
        onrm[i] = rsqrtf(fmaxf((float)outdeg[i], 1.0f));
        inrm[i] = rsqrtf(fmaxf((float)indeg[i], 1.0f));
    }
    if (i == 0) rowptr[n] = E;
}

__global__ void fill_kernel(const int* __restrict__ src, const int* __restrict__ dst,
                            int* __restrict__ fill, int* __restrict__ col, int E) {
    int i = blockIdx.x * blockDim.x + threadIdx.x;
    if (i < E) {
        int p = atomicAdd(fill + dst[i], 1);
        col[p] = src[i];
    }
}

// --------------------------- bf16x3 GEMM -----------------------------------
// X[M,N] (fp16) = f(A[M,K]) @ W[K,N], CTA tile 128 x N, K chunks of 32.
// MODE 0: f(a)[r,k] = a[r,k] * outnorm[r]
// MODE 1: f(a)[r,k] = relu(a[r,k]*innorm[r] + bprev[k]) * outnorm[r]
// bf16x3: D = Ah@Bh + Ah@Bl + Al@Bh, fp32 accum (mma.sync m16n8k16).

template<int K, int N, int MODE>
__global__ __launch_bounds__(256)
void gemm_mma_kernel(const float* __restrict__ A, const float* __restrict__ W,
                     const float* __restrict__ bprev,
                     const float* __restrict__ outnorm, const float* __restrict__ innorm,
                     __half* __restrict__ X, int M) {
    constexpr int BK = 32;
    constexpr int NCHUNK = K / BK;
    constexpr int WN = N / 2;
    constexpr int NT = WN / 8;
    constexpr int MT = 2;
    constexpr int P = 40;            // smem pitch in bf16 (80B, LDSM-clean)
    constexpr int A_HI = 0;
    constexpr int A_LO = 128 * P * 2;
    constexpr int W_HI = 2 * A_LO;
    constexpr int W_SZ = N * P * 2;
    constexpr int W_LO = W_HI + W_SZ;
    constexpr int BUFS = W_LO + W_SZ;
    constexpr int WE = N / 8;
    constexpr int LOGN = (N == 128) ? 7 : 6;

    extern __shared__ char smem[];
    const uint32_t sb = smem_u32(smem);
    const int tid = threadIdx.x;
    const int lane = tid & 31;
    const int wid = tid >> 5;
    const int warp_m = wid >> 1;
    const int warp_n = wid & 1;
    const int row0 = blockIdx.x * 128;

    const int arow = tid & 127;
    const int ahalf = tid >> 7;
    const int grow = row0 + arow;
    const bool valid = grow < M;
    const float on  = valid ? outnorm[grow] : 0.f;
    const float inn = (MODE == 1 && valid) ? innorm[grow] : 0.f;

    const int a_r = warp_m * 32 + ((lane >> 3) & 1) * 8 + (lane & 7);
    const int a_k = (lane >> 4) * 8;
    const int b_n = warp_n * WN + (lane >> 4) * 8 + (lane & 7);
    const int b_k = ((lane >> 3) & 1) * 8;

    float acc[MT][NT][4];
#pragma unroll
    for (int i = 0; i < MT; i++)
#pragma unroll
        for (int j = 0; j < NT; j++)
#pragma unroll
            for (int q = 0; q < 4; q++) acc[i][j][q] = 0.f;

    float4 av[4];
    float wv[WE];

    auto load_g = [&](int c) {
        const int kc = c * BK;
#pragma unroll
        for (int q = 0; q < 4; q++) {
            const int col = ahalf * 16 + q * 4;
            float4 v = make_float4(0.f, 0.f, 0.f, 0.f);
            if (valid) {
                v = *reinterpret_cast<const float4*>(A + (size_t)grow * K + kc + col);
                if (MODE == 0) {
                    v.x *= on; v.y *= on; v.z *= on; v.w *= on;
                } else {
                    float4 b = *reinterpret_cast<const float4*>(bprev + kc + col);
                    v.x = fmaxf(fmaf(v.x, inn, b.x), 0.f) * on;
                    v.y = fmaxf(fmaf(v.y, inn, b.y), 0.f) * on;
                    v.z = fmaxf(fmaf(v.z, inn, b.z), 0.f) * on;
                    v.w = fmaxf(fmaf(v.w, inn, b.w), 0.f) * on;
                }
            }
            av[q] = v;
        }
#pragma unroll
        for (int e = 0; e < WE; e++) {
            const int elem = tid + e * 256;
            const int n = elem & (N - 1);
            const int kk = elem >> LOGN;
            wv[e] = __ldg(W + (size_t)(kc + kk) * N + n);
        }
    };

    auto store_s = [&](int buf) {
        char* base = smem + buf * BUFS;
#pragma unroll
        for (int q = 0; q < 4; q++) {
            const int col = ahalf * 16 + q * 4;
            uint32_t h01, l01, h23, l23;
            split2(av[q].x, av[q].y, h01, l01);
            split2(av[q].z, av[q].w, h23, l23);
            const uint32_t off = (uint32_t)arow * (P * 2) + col * 2;
            *reinterpret_cast<uint2*>(base + A_HI + off) = make_uint2(h01, h23);
            *reinterpret_cast<uint2*>(base + A_LO + off) = make_uint2(l01, l23);
        }
#pragma unroll
        for (int e = 0; e < WE; e++) {
            const int elem = tid + e * 256;
            const int n = elem & (N - 1);
            const int kk = elem >> LOGN;
            uint16_t h, l;
            split1(wv[e], h, l);
            const uint32_t off = (uint32_t)n * (P * 2) + kk * 2;
            *reinterpret_cast<uint16_t*>(base + W_HI + off) = h;
            *reinterpret_cast<uint16_t*>(base + W_LO + off) = l;
        }
    };

    auto compute = [&](int buf) {
        const uint32_t ab = sb + buf * BUFS;
#pragma unroll
        for (int ks = 0; ks < 2; ks++) {
            uint32_t ah[MT][4], al[MT][4];
#pragma unroll
            for (int i = 0; i < MT; i++) {
                const uint32_t addr = ab + A_HI +
                    (uint32_t)(a_r + i * 16) * (P * 2) + (a_k + ks * 16) * 2;
                ldsm_x4(ah[i], addr);
                ldsm_x4(al[i], addr + A_LO);
            }
#pragma unroll
            for (int p = 0; p < NT / 2; p++) {
                uint32_t bh[4], bl[4];
                const uint32_t baddr = ab + W_HI +
                    (uint32_t)(b_n + p * 16) * (P * 2) + (b_k + ks * 16) * 2;
                ldsm_x4(bh, baddr);
                ldsm_x4(bl, baddr + W_SZ);
#pragma unroll
                for (int i = 0; i < MT; i++)
#pragma unroll
                    for (int jj = 0; jj < 2; jj++) {
                        float* d = acc[i][p * 2 + jj];
                        mma_bf16(d, ah[i], bh + jj * 2);
                        mma_bf16(d, ah[i], bl + jj * 2);
                        mma_bf16(d, al[i], bh + jj * 2);
                    }
            }
        }
    };

    load_g(0);
    store_s(0);
    __syncthreads();

    for (int c = 0; c < NCHUNK; c++) {
        if (c + 1 < NCHUNK) load_g(c + 1);
        compute(c & 1);
        if (c + 1 < NCHUNK) store_s((c + 1) & 1);
        __syncthreads();
    }

    // epilogue: fp32 acc -> fp16 X
#pragma unroll
    for (int i = 0; i < MT; i++) {
        const int r0 = row0 + warp_m * 32 + i * 16 + (lane >> 2);
#pragma unroll
        for (int j = 0; j < NT; j++) {
            const int n0 = warp_n * WN + j * 8 + (lane & 3) * 2;
            if (r0 < M)
                *reinterpret_cast<__half2*>(X + (size_t)r0 * N + n0) =
                    __floats2half2_rn(acc[i][j][0], acc[i][j][1]);
            if (r0 + 8 < M)
                *reinterpret_cast<__half2*>(X + (size_t)(r0 + 8) * N + n0) =
                    __floats2half2_rn(acc[i][j][2], acc[i][j][3]);
        }
    }
}

// ------------------------------ CSR gather ---------------------------------
// AGG[n] (fp32) = sum over e in [rowptr[n], rowptr[n+1]) of X[col[e]] (fp16)
// D/8 lanes per node; each lane loads 16B = 8 halves per edge.
// 2-edge unroll with 2 independent accumulator sets (R5 structure).

template<int D>
__global__ __launch_bounds__(256)
void gather_kernel(const __half* __restrict__ X, const int* __restrict__ rowptr,
                   const int* __restrict__ col, float* __restrict__ AGG, int Nn) {
    constexpr int LPN = D / 8;   // 16 for D=128, 8 for D=64
    int t = blockIdx.x * blockDim.x + threadIdx.x;
    int node = t / LPN;
    if (node >= Nn) return;
    int c = (t % LPN) * 8;
    int beg = __ldg(rowptr + node);
    int end = __ldg(rowptr + node + 1);

    float a0[8], a1[8];
#pragma unroll
    for (int q = 0; q < 8; q++) { a0[q] = 0.f; a1[q] = 0.f; }

    int e = beg;
    for (; e + 1 < end; e += 2) {
        int s0 = __ldg(col + e);
        int s1 = __ldg(col + e + 1);
        uint4 u0 = __ldg(reinterpret_cast<const uint4*>(X + (size_t)s0 * D + c));
        uint4 u1 = __ldg(reinterpret_cast<const uint4*>(X + (size_t)s1 * D + c));
        const __half2* h0 = reinterpret_cast<const __half2*>(&u0);
        const __half2* h1 = reinterpret_cast<const __half2*>(&u1);
#pragma unroll
        for (int q = 0; q < 4; q++) {
            float2 f0 = __half22float2(h0[q]);
            float2 f1 = __half22float2(h1[q]);
            a0[q * 2]     += f0.x;
            a0[q * 2 + 1] += f0.y;
            a1[q * 2]     += f1.x;
            a1[q * 2 + 1] += f1.y;
        }
    }
    if (e < end) {
        int s0 = __ldg(col + e);
        uint4 u0 = __ldg(reinterpret_cast<const uint4*>(X + (size_t)s0 * D + c));
        const __half2* h0 = reinterpret_cast<const __half2*>(&u0);
#pragma unroll
        for (int q = 0; q < 4; q++) {
            float2 f0 = __half22float2(h0[q]);
            a0[q * 2]     += f0.x;
            a0[q * 2 + 1] += f0.y;
        }
    }

    float4 r0, r1;
    r0.x = a0[0] + a1[0]; r0.y = a0[1] + a1[1];
    r0.z = a0[2] + a1[2]; r0.w = a0[3] + a1[3];
    r1.x = a0[4] + a1[4]; r1.y = a0[5] + a1[5];
    r1.z = a0[6] + a1[6]; r1.w = a0[7] + a1[7];
    float* dst = AGG + (size_t)node * D + c;
    *reinterpret_cast<float4*>(dst)     = r0;
    *reinterpret_cast<float4*>(dst + 4) = r1;
}

// ------------------------------- pooling -----------------------------------

__device__ __forceinline__ int lower_bound_dev(const int* __restrict__ a, int n, int v) {
    int lo = 0, hi = n;
    while (lo < hi) {
        int m = (lo + hi) >> 1;
        if (a[m] < v) lo = m + 1; else hi = m;
    }
    return lo;
}

__global__ void pool_kernel(const float* __restrict__ AGG, const float* __restrict__ innorm,
                            const float* __restrict__ b3, const int* __restrict__ gids,
                            float* __restrict__ out, int Nn) {
    int g = blockIdx.x;
    int lo = lower_bound_dev(gids, Nn, g);
    int hi = lower_bound_dev(gids, Nn, g + 1);
    int f = threadIdx.x & 63;
    int slot = threadIdx.x >> 6;
    float bf = b3[f];
    float sum = 0.f;
    for (int i = lo + slot; i < hi; i += 4)
        sum += fmaf(AGG[(size_t)i * 64 + f], innorm[i], bf);
    __shared__ float sh[256];
    sh[threadIdx.x] = sum;
    __syncthreads();
    if (slot == 0) {
        float tot = sh[f] + sh[64 + f] + sh[128 + f] + sh[192 + f];
        float cnt = (float)(hi - lo);
        out[g * 64 + f] = tot / fmaxf(cnt, 1.f);
    }
}

// ------------------------------- launch ------------------------------------

extern "C" void kernel_launch(void* const* d_in, const int* in_sizes, int n_in,
                              void* d_out, int out_size) {
    const float* emb = (const float*)d_in[0];
    const float* W1  = (const float*)d_in[1];
    const float* b1  = (const float*)d_in[2];
    const float* W2  = (const float*)d_in[3];
    const float* b2  = (const float*)d_in[4];
    const float* W3  = (const float*)d_in[5];
    const float* b3  = (const float*)d_in[6];
    const int*   src = (const int*)d_in[7];
    const int*   dst = (const int*)d_in[8];
    const int*   gid = (const int*)d_in[9];
    float* out = (float*)d_out;

    const int Nn = in_sizes[0] / 128;   // 100000
    const int E  = in_sizes[7];         // 1600000
    const int G  = out_size / 64;       // 64

    __half* X;
    float *AGG, *onrm, *inrm;
    int *indeg, *outdeg, *rowptr, *fillc, *colA, *bsums;
    cudaGetSymbolAddress((void**)&X,      g_X);
    cudaGetSymbolAddress((void**)&AGG,    g_AGG);
    cudaGetSymbolAddress((void**)&onrm,   g_outnorm);
    cudaGetSymbolAddress((void**)&inrm,   g_innorm);
    cudaGetSymbolAddress((void**)&indeg,  g_indeg);
    cudaGetSymbolAddress((void**)&outdeg, g_outdeg);
    cudaGetSymbolAddress((void**)&rowptr, g_rowptr);
    cudaGetSymbolAddress((void**)&fillc,  g_fill);
    cudaGetSymbolAddress((void**)&colA,   g_col);
    cudaGetSymbolAddress((void**)&bsums,  g_bsums);

    const int smem128 = 2 * (20480 + 2 * 128 * 80);  // 81920
    const int smem64  = 2 * (20480 + 2 * 64 * 80);   // 61440
    cudaFuncSetAttribute(gemm_mma_kernel<128, 128, 0>,
                         cudaFuncAttributeMaxDynamicSharedMemorySize, smem128);
    cudaFuncSetAttribute(gemm_mma_kernel<128, 64, 1>,
                         cudaFuncAttributeMaxDynamicSharedMemorySize, smem64);
    cudaFuncSetAttribute(gemm_mma_kernel<64, 64, 1>,
                         cudaFuncAttributeMaxDynamicSharedMemorySize, smem64);

    const int T = 256;
    const int gemm_grid = (Nn + 127) / 128;
    const int nb_scan = (Nn + SCAN_BS - 1) / SCAN_BS;

    // ---- CSR build + norms ----
    zero_int2_kernel<<<(Nn + T - 1) / T, T>>>(indeg, outdeg, Nn);
    hist_kernel<<<(E + T - 1) / T, T>>>(src, dst, outdeg, indeg, E);
    scanA_kernel<<<nb_scan, SCAN_BS>>>(indeg, rowptr, bsums, Nn);
    scanB_kernel<<<1, 256>>>(bsums, nb_scan);
    scanC_kernel<<<(Nn + T - 1) / T, T>>>(rowptr, fillc, bsums, outdeg, indeg,
                                          onrm, inrm, Nn, E);
    fill_kernel<<<(E + T - 1) / T, T>>>(src, dst, fillc, colA, E);

    // Layer 1: X1 = (emb * outnorm) @ W1 ; agg1 = gather(X1)
    gemm_mma_kernel<128, 128, 0><<<gemm_grid, T, smem128>>>(emb, W1, nullptr, onrm, inrm, X, Nn);
    gather_kernel<128><<<(Nn * 16 + T - 1) / T, T>>>(X, rowptr, colA, AGG, Nn);

    // Layer 2: X2 = relu(agg1*innorm + b1)*outnorm @ W2 ; agg2 = gather(X2)
    gemm_mma_kernel<128, 64, 1><<<gemm_grid, T, smem64>>>(AGG, W2, b1, onrm, inrm, X, Nn);
    gather_kernel<64><<<(Nn * 8 + T - 1) / T, T>>>(X, rowptr, colA, AGG, Nn);

    // Layer 3: X3 = relu(agg2*innorm + b2)*outnorm @ W3 ; agg3 = gather(X3)
    gemm_mma_kernel<64, 64, 1><<<gemm_grid, T, smem64>>>(AGG, W3, b2, onrm, inrm, X, Nn);
    gather_kernel<64><<<(Nn * 8 + T - 1) / T, T>>>(X, rowptr, colA, AGG, Nn);

    // Pool
    pool_kernel<<<G, T>>>(AGG, inrm, b3, gid, out, Nn);
}